// round 10
// baseline (speedup 1.0000x reference)
#include <cuda_runtime.h>
#include <cuda_bf16.h>
#include <cstdint>

#define BATCH      8192
#define STATE_DIM  322
#define N_NODES    256
#define ENTRIES    27
#define ACTION     4096

// Intermediates: y as bf16 [BATCH][256] (4 MB), Wf as bf16 [4096][256] (2 MB)
__device__ __nv_bfloat16 g_y [BATCH  * N_NODES];
__device__ __nv_bfloat16 g_wf[ACTION * N_NODES];

__device__ __forceinline__ uint32_t smem_u32(const void* p) {
    uint32_t a;
    asm("{ .reg .u64 t; cvta.to.shared.u64 t, %1; cvt.u32.u64 %0, t; }" : "=r"(a) : "l"(p));
    return a;
}
#define CP_ASYNC16(dst, src) \
    asm volatile("cp.async.cg.shared.global [%0], [%1], 16;" :: "r"(dst), "l"(src))
#define CP_COMMIT()  asm volatile("cp.async.commit_group;" ::: "memory")
#define CP_WAIT(N)   asm volatile("cp.async.wait_group %0;" :: "n"(N) : "memory")

__device__ __forceinline__ void ldmx4(uint32_t* r, uint32_t addr) {
    asm volatile("ldmatrix.sync.aligned.m8n8.x4.shared.b16 {%0,%1,%2,%3}, [%4];"
                 : "=r"(r[0]), "=r"(r[1]), "=r"(r[2]), "=r"(r[3]) : "r"(addr));
}
__device__ __forceinline__ void mma_bf16(float c[4], const uint32_t a[4],
                                         uint32_t b0, uint32_t b1) {
    asm volatile(
        "mma.sync.aligned.m16n8k16.row.col.f32.bf16.bf16.f32 "
        "{%0,%1,%2,%3}, {%4,%5,%6,%7}, {%8,%9}, {%0,%1,%2,%3};"
        : "+f"(c[0]), "+f"(c[1]), "+f"(c[2]), "+f"(c[3])
        : "r"(a[0]), "r"(a[1]), "r"(a[2]), "r"(a[3]), "r"(b0), "r"(b1));
}

// ---------------------------------------------------------------------------
// Kernel 1: fused prep (node forward + Wf bf16 convert)
// ---------------------------------------------------------------------------
#define R_PER_BLK  16
#define NODE_BLKS  (BATCH / R_PER_BLK)          // 512
#define CONV_BLKS  (ACTION * N_NODES / 1024)    // 1024

__global__ __launch_bounds__(256) void prep_kernel(
    const float* __restrict__ state, const float* __restrict__ W,
    const float* __restrict__ b,     const int*   __restrict__ idx,
    const float* __restrict__ Wf)
{
    if (blockIdx.x >= NODE_BLKS) {
        const int i = ((blockIdx.x - NODE_BLKS) * 256 + threadIdx.x) * 4;
        float4 v = *(const float4*)(Wf + i);
        __nv_bfloat162* p = (__nv_bfloat162*)(g_wf + i);
        p[0] = __floats2bfloat162_rn(v.x, v.y);
        p[1] = __floats2bfloat162_rn(v.z, v.w);
        return;
    }
    __shared__ float s[R_PER_BLK * STATE_DIM];
    const int t = threadIdx.x, row0 = blockIdx.x * R_PER_BLK;
    const float* sp = state + (long)row0 * STATE_DIM;
    for (int i = t; i < R_PER_BLK * STATE_DIM; i += 256) s[i] = sp[i];

    float w[ENTRIES]; int ix[ENTRIES];
#pragma unroll
    for (int e = 0; e < ENTRIES; e++) { w[e] = W[t*ENTRIES+e]; ix[e] = idx[t*ENTRIES+e]; }
    const float bb = b[t];
    __syncthreads();
#pragma unroll 4
    for (int r = 0; r < R_PER_BLK; r++) {
        const float* sr = s + r * STATE_DIM;
        float acc = bb;
#pragma unroll
        for (int e = 0; e < ENTRIES; e++) acc = fmaf(sr[ix[e]], w[e], acc);
        g_y[(long)(row0 + r) * N_NODES + t] = __float2bfloat16(tanhf(acc));
    }
}

// ---------------------------------------------------------------------------
// Kernel 2: persistent-B GEMM. out = 500*sigmoid(y @ Wf^T).
// Grid 32(n) x 8(m-strips). Each CTA: B tile 128n x 256k resident in smem
// (loaded once), sweeps 8 m-tiles of 128 rows streaming A via 2-stage
// cp.async. 256 threads, 8 warps 2m x 4n, warp tile 64x32. 2 CTAs/SM.
// A rows 144 B, B rows 528 B (both stride ≡ 4 mod 32 words: conflict-free
// ldmatrix phases).
// ---------------------------------------------------------------------------
#define BK       64
#define ROWA     144                   // A row: 72 bf16
#define ROWBB    528                   // B row: 264 bf16 (256 data + pad)
#define A_TILE   (128 * ROWA)          // 18432 B
#define SMEM_B_OFF (2 * A_TILE)        // 36864
#define B_TILE   (128 * ROWBB)         // 67584 B
#define SMEM_SZ  (SMEM_B_OFF + B_TILE) // 104448 B
#define M_TILES_PER_CTA 8

__global__ __launch_bounds__(256, 2) void gemm_sig_kernel(float* __restrict__ out)
{
    extern __shared__ char smem[];
    const uint32_t sb = smem_u32(smem);
    const int tid    = threadIdx.x;
    const int lane   = tid & 31;
    const int wid    = tid >> 5;
    const int warp_m = wid >> 2;       // 0..1
    const int warp_n = wid & 3;        // 0..3
    const int n0      = blockIdx.x * 128;
    const int m_strip = blockIdx.y * (128 * M_TILES_PER_CTA);

    const __nv_bfloat16* gB = g_wf + (size_t)n0 * N_NODES;

    // ---- prologue: B (4096 chunks) + A m-tile0/it0 (1024 chunks), one group
#pragma unroll
    for (int i = 0; i < 16; i++) {
        const int e = tid + i * 256, r = e >> 5, c = e & 31;
        CP_ASYNC16(sb + SMEM_B_OFF + r * ROWBB + c * 16,
                   (const void*)(gB + (size_t)r * N_NODES + c * 8));
    }
    {
        const __nv_bfloat16* gA = g_y + (size_t)m_strip * N_NODES;
#pragma unroll
        for (int i = 0; i < 4; i++) {
            const int e = tid + i * 256, r = e >> 3, c = e & 7;
            CP_ASYNC16(sb + r * ROWA + c * 16,
                       (const void*)(gA + (size_t)r * N_NODES + c * 8));
        }
    }
    CP_COMMIT();

    // fragment addresses
    uint32_t a_base[4];
#pragma unroll
    for (int mt = 0; mt < 4; mt++)
        a_base[mt] = sb + (warp_m * 64 + mt * 16 + (lane & 15)) * ROWA + (lane >> 4) * 16;
    uint32_t b_base[2];
#pragma unroll
    for (int p = 0; p < 2; p++)
        b_base[p] = sb + SMEM_B_OFF
                  + (warp_n * 32 + p * 16 + ((lane >> 4) & 1) * 8 + (lane & 7)) * ROWBB
                  + ((lane >> 3) & 1) * 16;

    const int frow = lane >> 2, fcol = lane & 3;
    int buf = 0;

    for (int jm = 0; jm < M_TILES_PER_CTA; jm++) {
        float acc[4][4][4] = {};

#pragma unroll
        for (int it = 0; it < 4; it++) {
            const int t = jm * 4 + it;
            if (t < 4 * M_TILES_PER_CTA - 1) {
                // prefetch next A chunk into buf^1
                const int nt_ = t + 1, njm = nt_ >> 2, nit = nt_ & 3;
                const __nv_bfloat16* gA =
                    g_y + (size_t)(m_strip + njm * 128) * N_NODES + nit * BK;
                const uint32_t dst = sb + (buf ^ 1) * A_TILE;
#pragma unroll
                for (int i = 0; i < 4; i++) {
                    const int e = tid + i * 256, r = e >> 3, c = e & 7;
                    CP_ASYNC16(dst + r * ROWA + c * 16,
                               (const void*)(gA + (size_t)r * N_NODES + c * 8));
                }
                CP_COMMIT();
                CP_WAIT(1);
            } else {
                CP_WAIT(0);
            }
            __syncthreads();

            const uint32_t soff = buf * A_TILE;
            const uint32_t boff = it * (BK * 2);   // byte offset in B row
#pragma unroll
            for (int kc = 0; kc < 4; kc++) {
                uint32_t a[4][4], bp[2][4];
#pragma unroll
                for (int mt = 0; mt < 4; mt++) ldmx4(a[mt], a_base[mt] + soff + kc * 32);
#pragma unroll
                for (int p = 0; p < 2; p++)    ldmx4(bp[p], b_base[p] + boff + kc * 32);
#pragma unroll
                for (int mt = 0; mt < 4; mt++)
#pragma unroll
                    for (int nt = 0; nt < 4; nt++)
                        mma_bf16(acc[mt][nt], a[mt],
                                 bp[nt >> 1][(nt & 1) * 2], bp[nt >> 1][(nt & 1) * 2 + 1]);
            }
            buf ^= 1;
            __syncthreads();
        }

        // epilogue for this m-tile (overlaps with already-issued next A load)
        const int m_base = m_strip + jm * 128 + warp_m * 64;
#pragma unroll
        for (int mt = 0; mt < 4; mt++) {
            const int m = m_base + mt * 16 + frow;
#pragma unroll
            for (int nt = 0; nt < 4; nt++) {
                const int n = n0 + warp_n * 32 + nt * 8 + 2 * fcol;
                float2 o0, o1;
                o0.x = __fdividef(500.0f, 1.0f + __expf(-acc[mt][nt][0]));
                o0.y = __fdividef(500.0f, 1.0f + __expf(-acc[mt][nt][1]));
                o1.x = __fdividef(500.0f, 1.0f + __expf(-acc[mt][nt][2]));
                o1.y = __fdividef(500.0f, 1.0f + __expf(-acc[mt][nt][3]));
                *(float2*)&out[(size_t)m * ACTION + n]       = o0;
                *(float2*)&out[(size_t)(m + 8) * ACTION + n] = o1;
            }
        }
    }
}

// ---------------------------------------------------------------------------
extern "C" void kernel_launch(void* const* d_in, const int* in_sizes, int n_in,
                              void* d_out, int out_size)
{
    const float* state = (const float*)d_in[0];
    const float* W     = (const float*)d_in[1];
    const float* b     = (const float*)d_in[2];
    const float* Wf    = (const float*)d_in[3];
    const int*   idx   = (const int*)  d_in[4];
    float*       out   = (float*)d_out;

    cudaFuncSetAttribute(gemm_sig_kernel,
                         cudaFuncAttributeMaxDynamicSharedMemorySize, SMEM_SZ);

    prep_kernel<<<NODE_BLKS + CONV_BLKS, 256>>>(state, W, b, idx, Wf);

    dim3 grid(ACTION / 128, BATCH / (128 * M_TILES_PER_CTA));
    gemm_sig_kernel<<<grid, 256, SMEM_SZ>>>(out);
}